// round 11
// baseline (speedup 1.0000x reference)
#include <cuda_runtime.h>
#include <cstdint>

#define TT   128
#define BLK  128
#define EPB  80          // elements per block: 4 warps x 10 groups x 2 elems
#define RSTRIDE 440      // floats per role block (duplicated-pair weights)

// role block (floats): Wih2 [5k][20j] pairs = 200, Whh2 = 200 at +200, bias2 = 40 at +400
#define FC_OFF 1320
#define FW1 (FC_OFF)
#define FB1 (FW1+640)
#define FW2 (FB1+32)
#define FB2 (FW2+1024)
#define FW3 (FB2+32)
#define FB3 (FW3+512)
#define FW4 (FB3+16)
#define FB4 (FW4+256)
#define FW5 (FB4+16)
#define FB5 (FW5+80)
#define S_TOTAL (FB5+5)   // 3933 floats = ~15.7 KB

typedef unsigned long long u64;

__device__ __forceinline__ float tanh_fast(float x) {
    float y;
    asm("tanh.approx.f32 %0, %1;" : "=f"(y) : "f"(x));
    return y;
}
// rows pre-scaled by 0.5 at staging: sigm(a) = fma(tanh(a'), 0.5, 0.5)
__device__ __forceinline__ float sigm_pre(float a_half) {
    return fmaf(tanh_fast(a_half), 0.5f, 0.5f);
}

__device__ __forceinline__ u64 ffma2(u64 a, u64 b, u64 c) {
    u64 d;
    asm("fma.rn.f32x2 %0, %1, %2, %3;" : "=l"(d) : "l"(a), "l"(b), "l"(c));
    return d;
}
__device__ __forceinline__ u64 pack2(float lo, float hi) {
    u64 d;
    asm("mov.b64 %0, {%1, %2};" : "=l"(d) : "f"(lo), "f"(hi));
    return d;
}
__device__ __forceinline__ void unpack2(u64 v, float& lo, float& hi) {
    asm("mov.b64 {%0, %1}, %2;" : "=f"(lo), "=f"(hi) : "l"(v));
}

// One LSTM step for TWO elements packed in f32x2 slots.
// sW (u64*): Wih2[5k*20j], Whh2 at +100; sB (u64*): bias2[20]. All pre-scaled on i/f/o rows.
__device__ __forceinline__ void cellp(const u64* __restrict__ sW,
                                      const u64* __restrict__ sB,
                                      const u64* __restrict__ in,   // [5] packed {xA,xB}
                                      u64* __restrict__ h2,         // [5] packed
                                      float* __restrict__ cA,
                                      float* __restrict__ cB,
                                      bool commit) {
    u64 g[20];
    {
        const ulonglong2* b2 = reinterpret_cast<const ulonglong2*>(sB);
        #pragma unroll
        for (int q = 0; q < 10; q++) {
            ulonglong2 v = b2[q];
            g[2*q] = v.x; g[2*q+1] = v.y;
        }
    }
    #pragma unroll
    for (int k = 0; k < 5; k++) {
        u64 xk = in[k];
        const ulonglong2* w2 = reinterpret_cast<const ulonglong2*>(sW + k * 20);
        #pragma unroll
        for (int q = 0; q < 10; q++) {
            ulonglong2 w = w2[q];
            g[2*q]   = ffma2(w.x, xk, g[2*q]);
            g[2*q+1] = ffma2(w.y, xk, g[2*q+1]);
        }
    }
    #pragma unroll
    for (int k = 0; k < 5; k++) {
        u64 hk = h2[k];
        const ulonglong2* u2 = reinterpret_cast<const ulonglong2*>(sW + 100 + k * 20);
        #pragma unroll
        for (int q = 0; q < 10; q++) {
            ulonglong2 u = u2[q];
            g[2*q]   = ffma2(u.x, hk, g[2*q]);
            g[2*q+1] = ffma2(u.y, hk, g[2*q+1]);
        }
    }
    float gA[20], gB[20];
    #pragma unroll
    for (int j = 0; j < 20; j++) unpack2(g[j], gA[j], gB[j]);

    #pragma unroll
    for (int m = 0; m < 5; m++) {
        float igA = sigm_pre(gA[m]);
        float fgA = sigm_pre(gA[5 + m]);
        float ggA = tanh_fast(gA[10 + m]);
        float ogA = sigm_pre(gA[15 + m]);
        float cmA = fmaf(fgA, cA[m], igA * ggA);
        float hmA = ogA * tanh_fast(cmA);

        float igB = sigm_pre(gB[m]);
        float fgB = sigm_pre(gB[5 + m]);
        float ggB = tanh_fast(gB[10 + m]);
        float ogB = sigm_pre(gB[15 + m]);
        float cmB = fmaf(fgB, cB[m], igB * ggB);
        float hmB = ogB * tanh_fast(cmB);

        cA[m] = commit ? cmA : cA[m];
        cB[m] = commit ? cmB : cB[m];
        h2[m] = commit ? pack2(hmA, hmB) : h2[m];
    }
}

// Load one 2-step chunk for BOTH elements and pack: dst[i] = {srcA[i], srcB[i]}, i<10.
__device__ __forceinline__ void load2p(u64* dst, const float* srcA, const float* srcB) {
    const float2* a2 = reinterpret_cast<const float2*>(srcA);
    const float2* b2 = reinterpret_cast<const float2*>(srcB);
    #pragma unroll
    for (int i = 0; i < 5; i++) {
        float2 a = __ldg(a2 + i);
        float2 b = __ldg(b2 + i);
        dst[2*i+0] = pack2(a.x, b.x);
        dst[2*i+1] = pack2(a.y, b.y);
    }
}

struct Params {
    const float *x1, *x2;
    const float *Wih1, *Whh1, *bih1, *bhh1;
    const float *Wih2a, *Whh2a, *bih2a, *bhh2a;
    const float *Wih2b, *Whh2b, *bih2b, *bhh2b;
    const float *W1, *b1, *W2, *b2, *W3, *b3, *W4, *b4, *W5, *b5;
    float* out;
    int B;
};

__global__ __launch_bounds__(BLK)
void dynrnn_kernel(Params p) {
    __shared__ __align__(16) float s[S_TOTAL];
    const int tid = threadIdx.x;

    // ---- weight staging: duplicated-pair transposed LSTM weights + scalar FC ----
    // sigmoid-gate rows (j<10 i/f, j>=15 o) pre-scaled by 0.5
    {
        const float* srcs[6] = { p.Wih1, p.Whh1, p.Wih2a, p.Whh2a, p.Wih2b, p.Whh2b };
        const int    offs[6] = { 0, 200, RSTRIDE, RSTRIDE+200, 2*RSTRIDE, 2*RSTRIDE+200 };
        for (int m = 0; m < 6; m++) {
            const float* W = srcs[m];
            int off = offs[m];
            for (int i = tid; i < 100; i += BLK) {
                int j = i / 5, k = i % 5;
                float sc = (j < 10 || j >= 15) ? 0.5f : 1.0f;
                float v = W[i] * sc;
                int fo = off + (k * 20 + j) * 2;
                s[fo] = v; s[fo + 1] = v;
            }
        }
        for (int i = tid; i < 20; i += BLK) {
            float sc = (i < 10 || i >= 15) ? 0.5f : 1.0f;
            float b0 = (p.bih1[i]  + p.bhh1[i])  * sc;
            float b1v = (p.bih2a[i] + p.bhh2a[i]) * sc;
            float b2v = (p.bih2b[i] + p.bhh2b[i]) * sc;
            s[0*RSTRIDE + 400 + 2*i] = b0;  s[0*RSTRIDE + 400 + 2*i + 1] = b0;
            s[1*RSTRIDE + 400 + 2*i] = b1v; s[1*RSTRIDE + 400 + 2*i + 1] = b1v;
            s[2*RSTRIDE + 400 + 2*i] = b2v; s[2*RSTRIDE + 400 + 2*i + 1] = b2v;
        }
        for (int i = tid; i < 640;  i += BLK) s[FW1 + i] = p.W1[i];
        for (int i = tid; i < 32;   i += BLK) s[FB1 + i] = p.b1[i];
        for (int i = tid; i < 1024; i += BLK) s[FW2 + i] = p.W2[i];
        for (int i = tid; i < 32;   i += BLK) s[FB2 + i] = p.b2[i];
        for (int i = tid; i < 512;  i += BLK) s[FW3 + i] = p.W3[i];
        for (int i = tid; i < 16;   i += BLK) s[FB3 + i] = p.b3[i];
        for (int i = tid; i < 256;  i += BLK) s[FW4 + i] = p.W4[i];
        for (int i = tid; i < 16;   i += BLK) s[FB4 + i] = p.b4[i];
        for (int i = tid; i < 80;   i += BLK) s[FW5 + i] = p.W5[i];
        for (int i = tid; i < 5;    i += BLK) s[FB5 + i] = p.b5[i];
    }
    __syncthreads();

    // ---- lane/role mapping: 3 lanes per 2-element group, 10 groups per warp ----
    const int l   = tid & 31;
    const int grp = l / 3;           // 0..9
    const int r   = l - 3 * grp;     // 0: lstm1, 1: lstm2a, 2: lstm2b
    const bool lane_ok = (l < 30);

    const int eA = blockIdx.x * EPB + (tid >> 5) * 20 + grp * 2;
    const int eB = eA + 1;
    const bool validA = lane_ok && (eA < p.B);
    const bool validB = lane_ok && (eB < p.B);
    const int ecA = (eA < p.B) ? eA : (p.B - 1);
    const int ecB = (eB < p.B) ? eB : (p.B - 1);

    const float* xbase = (r == 1) ? p.x2 : p.x1;
    const float* __restrict__ xpA = xbase + (size_t)ecA * (TT * 5);
    const float* __restrict__ xpB = xbase + (size_t)ecB * (TT * 5);
    const u64* __restrict__ sW = reinterpret_cast<const u64*>(s + r * RSTRIDE);
    const u64* __restrict__ sB = sW + 200;
    const bool isr2 = (r == 2);

    u64 h2[5], nh[5];
    float cA[5], cB[5];
    #pragma unroll
    for (int m = 0; m < 5; m++) { h2[m] = 0ull; nh[m] = 0ull; cA[m] = 0.0f; cB[m] = 0.0f; }

    u64 A2[10], B2[10];      // 2-step packed x double buffers
    load2p(A2, xpA, xpB);    // chunk 0 (steps 0,1)

    #pragma unroll 1
    for (int it = 0; it < 32; it++) {
        load2p(B2, xpA + (2 * it + 1) * 10, xpB + (2 * it + 1) * 10);
        #pragma unroll
        for (int tl = 0; tl < 2; tl++) {
            u64 in[5];
            #pragma unroll
            for (int j = 0; j < 5; j++) in[j] = isr2 ? nh[j] : A2[tl * 5 + j];
            bool commit = !(isr2 && (it == 0) && (tl == 0));
            cellp(sW, sB, in, h2, cA, cB, commit);
            #pragma unroll
            for (int j = 0; j < 5; j++) nh[j] = __shfl_up_sync(0xFFFFFFFFu, h2[j], 1);
        }
        int ci = 2 * it + 2; if (ci > 63) ci = 63;
        load2p(A2, xpA + ci * 10, xpB + ci * 10);
        #pragma unroll
        for (int tl = 0; tl < 2; tl++) {
            u64 in[5];
            #pragma unroll
            for (int j = 0; j < 5; j++) in[j] = isr2 ? nh[j] : B2[tl * 5 + j];
            cellp(sW, sB, in, h2, cA, cB, true);
            #pragma unroll
            for (int j = 0; j < 5; j++) nh[j] = __shfl_up_sync(0xFFFFFFFFu, h2[j], 1);
        }
    }

    // role-2 drains the pipeline: final step consumes h2a(127)
    if (isr2) {
        cellp(sW, sB, nh, h2, cA, cB, true);
    }

    // ---- gather results onto role-0 lanes ----
    // B2 holds chunk 63 (steps 126,127): last-step inputs packed at B2[5..9]
    u64 x2l[5], o2[5];
    #pragma unroll
    for (int j = 0; j < 5; j++) {
        x2l[j] = __shfl_down_sync(0xFFFFFFFFu, B2[5 + j], 1);  // role 1: x2 last (pair)
        o2[j]  = __shfl_down_sync(0xFFFFFFFFu, h2[j], 2);      // role 2: out2 (pair)
    }

    if (r == 0) {
        #pragma unroll 1
        for (int slot = 0; slot < 2; slot++) {
            bool v = slot == 0 ? validA : validB;
            if (!v) continue;
            int e = slot == 0 ? eA : eB;
            float a0[20];
            #pragma unroll
            for (int j = 0; j < 5; j++) {
                float lo, hi;
                unpack2(B2[5 + j], lo, hi);  a0[j]      = slot == 0 ? lo : hi;  // x1 last
                unpack2(x2l[j],    lo, hi);  a0[5 + j]  = slot == 0 ? lo : hi;  // x2 last
                unpack2(h2[j],     lo, hi);  a0[10 + j] = slot == 0 ? lo : hi;  // out1
                unpack2(o2[j],     lo, hi);  a0[15 + j] = slot == 0 ? lo : hi;  // out2
            }
            float a1[32];
            #pragma unroll
            for (int j = 0; j < 32; j++) {
                float acc = s[FB1 + j];
                #pragma unroll
                for (int k = 0; k < 20; k++) acc = fmaf(s[FW1 + j * 20 + k], a0[k], acc);
                a1[j] = fmaxf(acc, 0.0f);
            }
            float a2[32];
            #pragma unroll
            for (int j = 0; j < 32; j++) {
                float acc = s[FB2 + j];
                #pragma unroll
                for (int k = 0; k < 32; k++) acc = fmaf(s[FW2 + j * 32 + k], a1[k], acc);
                a2[j] = fmaxf(acc, 0.0f);
            }
            float a3[16];
            #pragma unroll
            for (int j = 0; j < 16; j++) {
                float acc = s[FB3 + j];
                #pragma unroll
                for (int k = 0; k < 32; k++) acc = fmaf(s[FW3 + j * 32 + k], a2[k], acc);
                a3[j] = fmaxf(acc, 0.0f);
            }
            float a4[16];
            #pragma unroll
            for (int j = 0; j < 16; j++) {
                float acc = s[FB4 + j];
                #pragma unroll
                for (int k = 0; k < 16; k++) acc = fmaf(s[FW4 + j * 16 + k], a3[k], acc);
                a4[j] = fmaxf(acc, 0.0f);
            }
            #pragma unroll
            for (int j = 0; j < 5; j++) {
                float acc = s[FB5 + j];
                #pragma unroll
                for (int k = 0; k < 16; k++) acc = fmaf(s[FW5 + j * 16 + k], a4[k], acc);
                p.out[(size_t)e * 5 + j] = acc;
            }
        }
    }
}

extern "C" void kernel_launch(void* const* d_in, const int* in_sizes, int n_in,
                              void* d_out, int out_size) {
    Params p;
    p.x1    = (const float*)d_in[0];
    p.x2    = (const float*)d_in[1];
    p.Wih1  = (const float*)d_in[2];
    p.Whh1  = (const float*)d_in[3];
    p.bih1  = (const float*)d_in[4];
    p.bhh1  = (const float*)d_in[5];
    p.Wih2a = (const float*)d_in[6];
    p.Whh2a = (const float*)d_in[7];
    p.bih2a = (const float*)d_in[8];
    p.bhh2a = (const float*)d_in[9];
    p.Wih2b = (const float*)d_in[10];
    p.Whh2b = (const float*)d_in[11];
    p.bih2b = (const float*)d_in[12];
    p.bhh2b = (const float*)d_in[13];
    p.W1 = (const float*)d_in[14];  p.b1 = (const float*)d_in[15];
    p.W2 = (const float*)d_in[16];  p.b2 = (const float*)d_in[17];
    p.W3 = (const float*)d_in[18];  p.b3 = (const float*)d_in[19];
    p.W4 = (const float*)d_in[20];  p.b4 = (const float*)d_in[21];
    p.W5 = (const float*)d_in[22];  p.b5 = (const float*)d_in[23];
    p.out = (float*)d_out;
    p.B   = in_sizes[0] / (TT * 5);

    int grid = (p.B + EPB - 1) / EPB;   // 205 blocks for B=16384 -> single wave
    dynrnn_kernel<<<grid, BLK>>>(p);
}

// round 12
// speedup vs baseline: 3.1309x; 3.1309x over previous
#include <cuda_runtime.h>
#include <cstdint>

#define TT   128
#define BLK  128
#define EPB  64          // elements per block: 4 warps x 16 pairs
#define RSTRIDE 220      // floats per role block in shared

// ---- shared layout (floats) ----
#define FC_OFF 660
#define FW1 (FC_OFF)
#define FB1 (FW1+640)
#define FW2 (FB1+32)
#define FB2 (FW2+1024)
#define FW3 (FB2+32)
#define FB3 (FW3+512)
#define FW4 (FB3+16)
#define FB4 (FW4+256)
#define FW5 (FB4+16)
#define FB5 (FW5+80)
#define S_TOTAL (FB5+5)   // 3273 floats = ~13.1 KB

typedef unsigned long long u64;

__device__ __forceinline__ float tanh_fast(float x) {
    float y;
    asm("tanh.approx.f32 %0, %1;" : "=f"(y) : "f"(x));
    return y;
}
// rows pre-scaled by 0.5 at staging: sigm(a) = fma(tanh(a'), 0.5, 0.5)
__device__ __forceinline__ float sigm_pre(float a_half) {
    return fmaf(tanh_fast(a_half), 0.5f, 0.5f);
}

__device__ __forceinline__ u64 ffma2(u64 a, u64 b, u64 c) {
    u64 d;
    asm("fma.rn.f32x2 %0, %1, %2, %3;" : "=l"(d) : "l"(a), "l"(b), "l"(c));
    return d;
}
__device__ __forceinline__ u64 bcast2(float x) {
    u64 d;
    asm("mov.b64 %0, {%1, %1};" : "=l"(d) : "f"(x));
    return d;
}
__device__ __forceinline__ void unpack2(u64 v, float& lo, float& hi) {
    asm("mov.b64 {%0, %1}, %2;" : "=f"(lo), "=f"(hi) : "l"(v));
}

// One H=5 LSTM cell step, packed gate math (identical structure to R8's cell).
// sW: WihT[5][20], WhhT at +100 (i/f/o rows pre-scaled 0.5); sB: pre-scaled fused bias[20].
__device__ __forceinline__ void cell(const float* __restrict__ sW,
                                     const float* __restrict__ sB,
                                     const float* __restrict__ in,
                                     float* __restrict__ h,
                                     float* __restrict__ c,
                                     bool commit) {
    u64 g[10];
    {
        const ulonglong2* b2 = reinterpret_cast<const ulonglong2*>(sB);
        #pragma unroll
        for (int q = 0; q < 5; q++) {
            ulonglong2 v = b2[q];
            g[2*q] = v.x; g[2*q+1] = v.y;
        }
    }
    #pragma unroll
    for (int k = 0; k < 5; k++) {
        u64 xk2 = bcast2(in[k]);
        const ulonglong2* w2 = reinterpret_cast<const ulonglong2*>(sW + k * 20);
        #pragma unroll
        for (int q = 0; q < 5; q++) {
            ulonglong2 w = w2[q];
            g[2*q]   = ffma2(w.x, xk2, g[2*q]);
            g[2*q+1] = ffma2(w.y, xk2, g[2*q+1]);
        }
    }
    #pragma unroll
    for (int k = 0; k < 5; k++) {
        u64 hk2 = bcast2(h[k]);
        const ulonglong2* u2 = reinterpret_cast<const ulonglong2*>(sW + 100 + k * 20);
        #pragma unroll
        for (int q = 0; q < 5; q++) {
            ulonglong2 u = u2[q];
            g[2*q]   = ffma2(u.x, hk2, g[2*q]);
            g[2*q+1] = ffma2(u.y, hk2, g[2*q+1]);
        }
    }
    float ga[20];
    #pragma unroll
    for (int q = 0; q < 10; q++) unpack2(g[q], ga[2*q], ga[2*q+1]);

    #pragma unroll
    for (int m = 0; m < 5; m++) {
        float ig = sigm_pre(ga[m]);
        float fg = sigm_pre(ga[5 + m]);
        float gg = tanh_fast(ga[10 + m]);
        float og = sigm_pre(ga[15 + m]);
        float cm = fmaf(fg, c[m], ig * gg);
        float hm = og * tanh_fast(cm);
        c[m] = commit ? cm : c[m];
        h[m] = commit ? hm : h[m];
    }
}

// Load one 2-timestep chunk (10 floats, 8B-aligned) with LDG.64.
__device__ __forceinline__ void load2(float* dst, const float* src) {
    const float2* s2 = reinterpret_cast<const float2*>(src);
    #pragma unroll
    for (int i = 0; i < 5; i++) {
        float2 v = __ldg(s2 + i);
        dst[2*i+0] = v.x; dst[2*i+1] = v.y;
    }
}

struct Params {
    const float *x1, *x2;
    const float *Wih1, *Whh1, *bih1, *bhh1;
    const float *Wih2a, *Whh2a, *bih2a, *bhh2a;
    const float *Wih2b, *Whh2b, *bih2b, *bhh2b;
    const float *W1, *b1, *W2, *b2, *W3, *b3, *W4, *b4, *W5, *b5;
    float* out;
    int B;
};

__global__ __launch_bounds__(BLK)
void dynrnn_kernel(Params p) {
    __shared__ float s[S_TOTAL];
    const int tid = threadIdx.x;

    // ---- cooperative weight staging (transposed LSTM weights, role blocks) ----
    // sigmoid-gate rows (j<10 i/f, j>=15 o) pre-scaled by 0.5
    {
        const float* srcs[6] = { p.Wih1, p.Whh1, p.Wih2a, p.Whh2a, p.Wih2b, p.Whh2b };
        const int    offs[6] = { 0, 100, RSTRIDE, RSTRIDE+100, 2*RSTRIDE, 2*RSTRIDE+100 };
        for (int m = 0; m < 6; m++) {
            const float* W = srcs[m];
            int off = offs[m];
            for (int i = tid; i < 100; i += BLK) {
                int j = i / 5, k = i % 5;
                float sc = (j < 10 || j >= 15) ? 0.5f : 1.0f;
                s[off + k * 20 + j] = W[i] * sc;
            }
        }
        for (int i = tid; i < 20; i += BLK) {
            float sc = (i < 10 || i >= 15) ? 0.5f : 1.0f;
            s[0*RSTRIDE + 200 + i] = (p.bih1[i]  + p.bhh1[i])  * sc;
            s[1*RSTRIDE + 200 + i] = (p.bih2a[i] + p.bhh2a[i]) * sc;
            s[2*RSTRIDE + 200 + i] = (p.bih2b[i] + p.bhh2b[i]) * sc;
        }
        for (int i = tid; i < 640;  i += BLK) s[FW1 + i] = p.W1[i];
        for (int i = tid; i < 32;   i += BLK) s[FB1 + i] = p.b1[i];
        for (int i = tid; i < 1024; i += BLK) s[FW2 + i] = p.W2[i];
        for (int i = tid; i < 32;   i += BLK) s[FB2 + i] = p.b2[i];
        for (int i = tid; i < 512;  i += BLK) s[FW3 + i] = p.W3[i];
        for (int i = tid; i < 16;   i += BLK) s[FB3 + i] = p.b3[i];
        for (int i = tid; i < 256;  i += BLK) s[FW4 + i] = p.W4[i];
        for (int i = tid; i < 16;   i += BLK) s[FB4 + i] = p.b4[i];
        for (int i = tid; i < 80;   i += BLK) s[FW5 + i] = p.W5[i];
        for (int i = tid; i < 5;    i += BLK) s[FB5 + i] = p.b5[i];
    }
    __syncthreads();

    // ---- lane mapping: 2 lanes per element, 16 elements per warp ----
    // even lane (sub=0): lstm1 (cell#1) + lstm2a (cell#2)
    // odd  lane (sub=1): lstm2b (cell#1, one step behind via shfl)
    const int l   = tid & 31;
    const int sub = l & 1;
    const int pr  = l >> 1;          // 0..15

    const int e = blockIdx.x * EPB + (tid >> 5) * 16 + pr;
    const bool valid = (e < p.B);
    const int ec = valid ? e : (p.B - 1);

    const float* __restrict__ xp1 = p.x1 + (size_t)ec * (TT * 5);
    const float* __restrict__ xp2 = p.x2 + (size_t)ec * (TT * 5);
    // cell#1 weights: role0 (lstm1) on even lanes, role2 (lstm2b) on odd lanes
    const float* __restrict__ sWa = s + (sub ? 2 * RSTRIDE : 0);
    const float* __restrict__ sBa = sWa + 200;
    // cell#2 weights: role1 (lstm2a) — all lanes read the same block (broadcast)
    const float* __restrict__ sWb = s + RSTRIDE;
    const float* __restrict__ sBb = sWb + 200;
    const bool odd = (sub == 1);

    float h1[5], c1[5];   // cell#1 state: lstm1 (even) / lstm2b (odd)
    float h2[5], c2[5];   // cell#2 state: lstm2a (even); garbage on odd
    float nh[5];
    #pragma unroll
    for (int m = 0; m < 5; m++) {
        h1[m] = 0.0f; c1[m] = 0.0f; h2[m] = 0.0f; c2[m] = 0.0f; nh[m] = 0.0f;
    }

    float xA1[10], xB1[10], xA2[10], xB2[10];   // 2-step double buffers per stream
    load2(xA1, xp1);     // chunk 0 of x1
    load2(xA2, xp2);     // chunk 0 of x2

    #pragma unroll 1
    for (int it = 0; it < 32; it++) {
        load2(xB1, xp1 + (2 * it + 1) * 10);
        load2(xB2, xp2 + (2 * it + 1) * 10);
        #pragma unroll
        for (int tl = 0; tl < 2; tl++) {
            float in[5];
            #pragma unroll
            for (int j = 0; j < 5; j++) in[j] = odd ? nh[j] : xA1[tl * 5 + j];
            bool commit = !(odd && (it == 0) && (tl == 0));   // lstm2b warm-up skip
            cell(sWa, sBa, in, h1, c1, commit);
            cell(sWb, sBb, &xA2[tl * 5], h2, c2, true);       // lstm2a (odd: garbage)
            #pragma unroll
            for (int j = 0; j < 5; j++) nh[j] = __shfl_up_sync(0xFFFFFFFFu, h2[j], 1);
        }
        int ci = 2 * it + 2; if (ci > 63) ci = 63;   // clamped redundant load on last iter
        load2(xA1, xp1 + ci * 10);
        load2(xA2, xp2 + ci * 10);
        #pragma unroll
        for (int tl = 0; tl < 2; tl++) {
            float in[5];
            #pragma unroll
            for (int j = 0; j < 5; j++) in[j] = odd ? nh[j] : xB1[tl * 5 + j];
            cell(sWa, sBa, in, h1, c1, true);
            cell(sWb, sBb, &xB2[tl * 5], h2, c2, true);
            #pragma unroll
            for (int j = 0; j < 5; j++) nh[j] = __shfl_up_sync(0xFFFFFFFFu, h2[j], 1);
        }
    }

    // lstm2b drain: consumes h2a(127). Even lanes execute but don't commit.
    cell(sWa, sBa, nh, h1, c1, odd);

    // ---- gather: out2 (odd lane h1) onto even lanes ----
    float o2[5];
    #pragma unroll
    for (int j = 0; j < 5; j++) {
        o2[j] = __shfl_down_sync(0xFFFFFFFFu, h1[j], 1);
    }

    if (valid && sub == 0) {
        // xB1/xB2 hold chunk 63 (steps 126,127): last-step inputs at [5..9]
        float a0[20];
        #pragma unroll
        for (int j = 0; j < 5; j++) {
            a0[j]      = xB1[5 + j];  // x1 last
            a0[5 + j]  = xB2[5 + j];  // x2 last
            a0[10 + j] = h1[j];       // out1 (lstm1)
            a0[15 + j] = o2[j];       // out2 (lstm2b)
        }
        float a1[32];
        #pragma unroll
        for (int j = 0; j < 32; j++) {
            float acc = s[FB1 + j];
            #pragma unroll
            for (int k = 0; k < 20; k++) acc = fmaf(s[FW1 + j * 20 + k], a0[k], acc);
            a1[j] = fmaxf(acc, 0.0f);
        }
        float a2[32];
        #pragma unroll
        for (int j = 0; j < 32; j++) {
            float acc = s[FB2 + j];
            #pragma unroll
            for (int k = 0; k < 32; k++) acc = fmaf(s[FW2 + j * 32 + k], a1[k], acc);
            a2[j] = fmaxf(acc, 0.0f);
        }
        float a3[16];
        #pragma unroll
        for (int j = 0; j < 16; j++) {
            float acc = s[FB3 + j];
            #pragma unroll
            for (int k = 0; k < 32; k++) acc = fmaf(s[FW3 + j * 32 + k], a2[k], acc);
            a3[j] = fmaxf(acc, 0.0f);
        }
        float a4[16];
        #pragma unroll
        for (int j = 0; j < 16; j++) {
            float acc = s[FB4 + j];
            #pragma unroll
            for (int k = 0; k < 16; k++) acc = fmaf(s[FW4 + j * 16 + k], a3[k], acc);
            a4[j] = fmaxf(acc, 0.0f);
        }
        #pragma unroll
        for (int j = 0; j < 5; j++) {
            float acc = s[FB5 + j];
            #pragma unroll
            for (int k = 0; k < 16; k++) acc = fmaf(s[FW5 + j * 16 + k], a4[k], acc);
            p.out[(size_t)e * 5 + j] = acc;
        }
    }
}

extern "C" void kernel_launch(void* const* d_in, const int* in_sizes, int n_in,
                              void* d_out, int out_size) {
    Params p;
    p.x1    = (const float*)d_in[0];
    p.x2    = (const float*)d_in[1];
    p.Wih1  = (const float*)d_in[2];
    p.Whh1  = (const float*)d_in[3];
    p.bih1  = (const float*)d_in[4];
    p.bhh1  = (const float*)d_in[5];
    p.Wih2a = (const float*)d_in[6];
    p.Whh2a = (const float*)d_in[7];
    p.bih2a = (const float*)d_in[8];
    p.bhh2a = (const float*)d_in[9];
    p.Wih2b = (const float*)d_in[10];
    p.Whh2b = (const float*)d_in[11];
    p.bih2b = (const float*)d_in[12];
    p.bhh2b = (const float*)d_in[13];
    p.W1 = (const float*)d_in[14];  p.b1 = (const float*)d_in[15];
    p.W2 = (const float*)d_in[16];  p.b2 = (const float*)d_in[17];
    p.W3 = (const float*)d_in[18];  p.b3 = (const float*)d_in[19];
    p.W4 = (const float*)d_in[20];  p.b4 = (const float*)d_in[21];
    p.W5 = (const float*)d_in[22];  p.b5 = (const float*)d_in[23];
    p.out = (float*)d_out;
    p.B   = in_sizes[0] / (TT * 5);

    int grid = (p.B + EPB - 1) / EPB;   // 256 blocks for B=16384 -> single wave
    dynrnn_kernel<<<grid, BLK>>>(p);
}